// round 13
// baseline (speedup 1.0000x reference)
#include <cuda_runtime.h>
#include <cstdint>

#define Tn 4096   // B*S tokens
#define Dn 1024
#define En 8
#define Fn 4096
#define Bb 8
#define Sn 512

// ---------------- scratch (device globals; no allocations) ----------------
__device__ float g_lin[Tn * Dn];
__device__ float g_h[2 * Tn * Fn];
__device__ float g_moe[2 * Tn * Dn];   // per-topk-slot expert outputs (no atomics)
__device__ float g_wc[Dn * En];        // folded gate: x@Wc = gate logits
__device__ float g_bc[En];
__device__ int   g_tok[2 * Tn];
__device__ int   g_tk[2 * Tn];         // which top-k slot (0/1) this routing entry is
__device__ float g_tw[2 * Tn];
__device__ int   g_cnt[En], g_off[En], g_fill[En];
__device__ int   g_gi[Tn * 2];
__device__ float g_gw[Tn * 2];
__device__ float g_sent[Bb * Dn];

// ---------------- helpers ----------------
__device__ __forceinline__ uint32_t s2u(const void* p) {
    uint32_t a;
    asm("{ .reg .u64 t; cvta.to.shared.u64 t, %1; cvt.u32.u64 %0, t; }" : "=r"(a) : "l"(p));
    return a;
}
__device__ __forceinline__ void mma8(float* c, const uint32_t* a,
                                     uint32_t b0, uint32_t b1) {
    asm volatile(
        "mma.sync.aligned.m16n8k8.row.col.f32.tf32.tf32.f32 "
        "{%0,%1,%2,%3},{%4,%5,%6,%7},{%8,%9},{%0,%1,%2,%3};"
        : "+f"(c[0]), "+f"(c[1]), "+f"(c[2]), "+f"(c[3])
        : "r"(a[0]), "r"(a[1]), "r"(a[2]), "r"(a[3]), "r"(b0), "r"(b1));
}
__device__ __forceinline__ void ldmx4(uint32_t* r, uint32_t a) {
    asm volatile("ldmatrix.sync.aligned.m8n8.x4.shared.b16 {%0,%1,%2,%3},[%4];"
                 : "=r"(r[0]), "=r"(r[1]), "=r"(r[2]), "=r"(r[3]) : "r"(a));
}
#define CPA(dst, src) \
    asm volatile("cp.async.cg.shared.global [%0], [%1], 16;" :: "r"(dst), "l"(src) : "memory")
#define CPCOMMIT() asm volatile("cp.async.commit_group;" ::: "memory")
#define CPWAIT0()  asm volatile("cp.async.wait_group 0;" ::: "memory")
#define CPWAIT1()  asm volatile("cp.async.wait_group 1;" ::: "memory")

// ---------------- Wc = W^T @ Wg (exact fp32), bc = b @ Wg ----------------
__global__ void __launch_bounds__(256) k_wc(const float* __restrict__ W,
                                            const float* __restrict__ Wg,
                                            const float* __restrict__ b) {
    __shared__ float swg[Dn * En];
    for (int i = threadIdx.x; i < Dn * En; i += 256) swg[i] = Wg[i];
    __syncthreads();
    int d = blockIdx.x * 256 + threadIdx.x;
    float acc[En] = {};
    for (int ep = 0; ep < Dn; ep++) {
        float wv = W[(size_t)ep * Dn + d];
        const float* wg = &swg[ep * En];
#pragma unroll
        for (int e = 0; e < En; e++) acc[e] += wv * wg[e];
    }
#pragma unroll
    for (int e = 0; e < En; e++) g_wc[d * En + e] = acc[e];
    if (blockIdx.x == 0 && threadIdx.x < En) {
        float s = 0.f;
        for (int ep = 0; ep < Dn; ep++) s += b[ep] * swg[ep * En + threadIdx.x];
        g_bc[threadIdx.x] = s;
    }
}

// ---------------- init: zero expert counters only ----------------
__global__ void k_init() {
    if (threadIdx.x < En) g_cnt[threadIdx.x] = 0;
}

// ---------------- gate from x via folded Wc (exact fp32 top-2) -------------
__global__ void k_gate2(const float* __restrict__ x) {
    int warp = (blockIdx.x * blockDim.x + threadIdx.x) >> 5;
    int lane = threadIdx.x & 31;
    if (warp >= Tn) return;
    const float* xr = &x[(size_t)warp * Dn];
    float p[En] = {};
    for (int i = lane; i < Dn; i += 32) {
        float v = xr[i];
        const float* w = &g_wc[i * En];
#pragma unroll
        for (int e = 0; e < En; e++) p[e] += v * w[e];
    }
#pragma unroll
    for (int o = 16; o; o >>= 1)
#pragma unroll
        for (int e = 0; e < En; e++) p[e] += __shfl_xor_sync(0xffffffffu, p[e], o);
    if (lane == 0) {
#pragma unroll
        for (int e = 0; e < En; e++) p[e] += g_bc[e];
        int i1 = 0;
        for (int e = 1; e < En; e++) if (p[e] > p[i1]) i1 = e;
        int i2 = -1;
        for (int e = 0; e < En; e++)
            if (e != i1 && (i2 < 0 || p[e] > p[i2])) i2 = e;
        float w1 = 1.f / (1.f + expf(p[i2] - p[i1]));
        g_gi[warp * 2] = i1; g_gi[warp * 2 + 1] = i2;
        g_gw[warp * 2] = w1; g_gw[warp * 2 + 1] = 1.f - w1;
        atomicAdd(&g_cnt[i1], 1);
        atomicAdd(&g_cnt[i2], 1);
    }
}

__global__ void k_off() {
    int a = 0;
    for (int e = 0; e < En; e++) { g_off[e] = a; a += g_cnt[e]; g_fill[e] = 0; }
}

__global__ void k_scatter() {
    int t = blockIdx.x * blockDim.x + threadIdx.x;
    if (t >= Tn) return;
#pragma unroll
    for (int k = 0; k < 2; k++) {
        int e = g_gi[t * 2 + k];
        int slot = g_off[e] + atomicAdd(&g_fill[e], 1);
        g_tok[slot] = t;
        g_tk[slot]  = k;
        g_tw[slot]  = g_gw[t * 2 + k];
    }
}

// ==== lin = x @ W^T + b : pipelined ldmatrix GEMM (proven 92us, untouched) ==
__global__ void __launch_bounds__(256) k_lin(const float* __restrict__ x,
                                             const float* __restrict__ W,
                                             const float* __restrict__ bias)
{
    extern __shared__ float sm[];
    constexpr int STR = 36;
    constexpr uint32_t ASTG = 128 * STR * 4, BSTG = 128 * STR * 4;
    float* Asm = sm;                      // [2][128][36]
    float* Bsm = sm + 2 * 128 * STR;      // [2][128][36]
    int row0 = blockIdx.x * 128, col0 = blockIdx.y * 128;
    int tid = threadIdx.x, warp = tid >> 5, lane = tid & 31;
    int warpM = warp >> 1, warpN = warp & 1;
    int grp = lane >> 2, tig = lane & 3;
    int mBase = warpM * 32, nBase = warpN * 64;
    uint32_t Au = s2u(Asm), Bu = s2u(Bsm);

    int ar = tid >> 1, ac = (tid & 1) * 16;
    const float* asrc = x + (size_t)(row0 + ar) * Dn + ac;
    const float* bsrc = W + (size_t)(col0 + ar) * Dn + ac;
    uint32_t aDst0 = Au + ((uint32_t)ar * STR + ac) * 4;
    uint32_t bDst0 = Bu + ((uint32_t)ar * STR + ac) * 4;

    auto stage = [&](int it) {
        int buf = it & 1;
        const float* as = asrc + it * 32;
        const float* bs = bsrc + it * 32;
        uint32_t ad = aDst0 + buf * ASTG, bd = bDst0 + buf * BSTG;
#pragma unroll
        for (int j = 0; j < 4; j++) CPA(ad + j * 16, as + j * 4);
#pragma unroll
        for (int j = 0; j < 4; j++) CPA(bd + j * 16, bs + j * 4);
        CPCOMMIT();
    };
    stage(0);
    stage(1);

    uint32_t aB0 = Au + (uint32_t)((mBase + (lane & 7) + 8 * ((lane >> 3) & 1)) * STR
                                   + 4 * (lane >> 4)) * 4;
    uint32_t aB1 = aB0 + 16 * STR * 4;
    uint32_t bB[4];
#pragma unroll
    for (int p = 0; p < 4; p++)
        bB[p] = Bu + (uint32_t)((nBase + p * 16 + (lane & 7) + 8 * (lane >> 4)) * STR
                                + 4 * ((lane >> 3) & 1)) * 4;

    float cc[2][8][4] = {};
    constexpr int NK = Dn / 32;
    for (int it = 0; it < NK; ++it) {
        if (it < NK - 1) { CPWAIT1(); } else { CPWAIT0(); }
        __syncthreads();
        uint32_t so = (uint32_t)(it & 1) * ASTG;
#pragma unroll
        for (int ks = 0; ks < 32; ks += 8) {
            uint32_t af0[4], af1[4], bf[4][4];
            ldmx4(af0, aB0 + so + ks * 4);
            ldmx4(af1, aB1 + so + ks * 4);
#pragma unroll
            for (int p = 0; p < 4; p++) ldmx4(bf[p], bB[p] + so + ks * 4);
#pragma unroll
            for (int p = 0; p < 4; p++) {
                mma8(cc[0][2 * p],     af0, bf[p][0], bf[p][1]);
                mma8(cc[0][2 * p + 1], af0, bf[p][2], bf[p][3]);
                mma8(cc[1][2 * p],     af1, bf[p][0], bf[p][1]);
                mma8(cc[1][2 * p + 1], af1, bf[p][2], bf[p][3]);
            }
        }
        __syncthreads();
        if (it + 2 < NK) stage(it + 2);
    }
#pragma unroll
    for (int mt = 0; mt < 2; mt++)
#pragma unroll
    for (int half = 0; half < 2; half++) {
        int r = row0 + mBase + mt * 16 + grp + half * 8;
        float* o = g_lin + (size_t)r * Dn + col0;
#pragma unroll
        for (int nt = 0; nt < 8; nt++) {
            int c = nBase + nt * 8 + 2 * tig;
            float2 v;
            v.x = cc[mt][nt][half * 2 + 0] + bias[col0 + c];
            v.y = cc[mt][nt][half * 2 + 1] + bias[col0 + c + 1];
            *(float2*)(o + c) = v;
        }
    }
}

// ==== ffn GEMMs: R12 kernels + min-3-blocks/SM occupancy (the R13 change) ===
// MODE 1: g_h = relu(lin[g_tok] @ w1[e] + b1)      (KD=Dn, NT=Fn)
// MODE 2: g_moe[kk][tok] = gw * (g_h @ w2[e] + b2) (KD=Fn, NT=Dn)
template<int KD, int NT, int MODE>
__global__ void __launch_bounds__(256, 3) pipe_ffn(const float* __restrict__ Bw,
                                                   const float* __restrict__ bias)
{
    extern __shared__ float sm[];
    constexpr int ASTR = 36, BSTR = 136;
    constexpr uint32_t ASTG = 128 * ASTR * 4, BSTG = 32 * BSTR * 4;
    float* Asm = sm;                               // [2][128][36]  ([m][k])
    float* Bsm = sm + 2 * 128 * ASTR;              // [2][32][136]  ([k][n])

    int e = blockIdx.z, cnt = g_cnt[e], row0 = blockIdx.x * 128;
    if (row0 >= cnt) return;
    int off = g_off[e], col0 = blockIdx.y * 128;
    int tid = threadIdx.x, warp = tid >> 5, lane = tid & 31;
    int warpM = warp >> 1, warpN = warp & 1;
    int grp = lane >> 2, tig = lane & 3;
    int mBase = warpM * 32, nBase = warpN * 64;

    uint32_t Au = s2u(Asm), Bu = s2u(Bsm);

    int ar = tid >> 1, ac = (tid & 1) * 16;
    const float* asrc;
    if (MODE == 1) {
        int r = row0 + ar;
        int tok = (r < cnt) ? g_tok[off + r] : g_tok[off];
        asrc = g_lin + (size_t)tok * KD;
    } else {
        int s = off + row0 + ar; if (s >= 2 * Tn) s = 0;
        asrc = g_h + (size_t)s * KD;
    }
    int br = tid >> 3, bc4 = (tid & 7) * 4;
    const float* bsrc = Bw + (size_t)e * KD * NT + (size_t)br * NT + col0 + bc4;

    uint32_t aDst0 = Au + ((uint32_t)ar * ASTR + ac) * 4;
    uint32_t bDst0 = Bu + ((uint32_t)br * BSTR + bc4) * 4;

    auto stage = [&](int it) {
        int buf = it & 1;
        int k0 = it * 32;
        uint32_t ad = aDst0 + buf * ASTG;
        const float* as = asrc + k0 + ac;
#pragma unroll
        for (int j = 0; j < 4; j++) CPA(ad + j * 16, as + j * 4);
        uint32_t bd = bDst0 + buf * BSTG;
        const float* bs = bsrc + (size_t)k0 * NT;
#pragma unroll
        for (int j = 0; j < 4; j++) CPA(bd + j * 128, bs + j * 32);
        CPCOMMIT();
    };

    stage(0);
    stage(1);

    float cc[2][8][4] = {};
    constexpr int NK = KD / 32;
    for (int it = 0; it < NK; ++it) {
        if (it == NK - 1) { CPWAIT0(); } else { CPWAIT1(); }
        __syncthreads();
        int buf = it & 1;
        const float* Af = Asm + buf * 128 * ASTR;
        const float* Bf = Bsm + buf * 32 * BSTR;
#pragma unroll
        for (int ks = 0; ks < 32; ks += 8) {
            uint32_t af[2][4];
#pragma unroll
            for (int mt = 0; mt < 2; mt++) {
                int m = mBase + mt * 16 + grp;
                af[mt][0] = __float_as_uint(Af[m * ASTR + ks + tig]);
                af[mt][1] = __float_as_uint(Af[(m + 8) * ASTR + ks + tig]);
                af[mt][2] = __float_as_uint(Af[m * ASTR + ks + tig + 4]);
                af[mt][3] = __float_as_uint(Af[(m + 8) * ASTR + ks + tig + 4]);
            }
#pragma unroll
            for (int nt = 0; nt < 8; nt++) {
                int n = nBase + nt * 8 + grp;
                uint32_t b0 = __float_as_uint(Bf[(ks + tig) * BSTR + n]);
                uint32_t b1 = __float_as_uint(Bf[(ks + tig + 4) * BSTR + n]);
                mma8(cc[0][nt], af[0], b0, b1);
                mma8(cc[1][nt], af[1], b0, b1);
            }
        }
        __syncthreads();
        if (it + 2 < NK) stage(it + 2);
    }

#pragma unroll
    for (int mt = 0; mt < 2; mt++)
#pragma unroll
    for (int half = 0; half < 2; half++) {
        int r = row0 + mBase + mt * 16 + grp + half * 8;
        if (r >= cnt) continue;
        int slot = off + r;
        if (MODE == 1) {
            float* o = g_h + (size_t)slot * Fn + col0;
#pragma unroll
            for (int nt = 0; nt < 8; nt++) {
                int c = nBase + nt * 8 + 2 * tig;
                float2 v;
                v.x = fmaxf(cc[mt][nt][half * 2 + 0] + bias[e * Fn + col0 + c], 0.f);
                v.y = fmaxf(cc[mt][nt][half * 2 + 1] + bias[e * Fn + col0 + c + 1], 0.f);
                *(float2*)(o + c) = v;
            }
        } else {
            int tok = g_tok[slot];
            int kk  = g_tk[slot];
            float gw = g_tw[slot];
            float* o = g_moe + ((size_t)kk * Tn + tok) * Dn + col0;
#pragma unroll
            for (int nt = 0; nt < 8; nt++) {
                int c = nBase + nt * 8 + 2 * tig;
                float2 v;
                v.x = gw * (cc[mt][nt][half * 2 + 0] + bias[e * Dn + col0 + c]);
                v.y = gw * (cc[mt][nt][half * 2 + 1] + bias[e * Dn + col0 + c + 1]);
                *(float2*)(o + c) = v;
            }
        }
    }
}

// ---------------- mean pool (x + moe0 + moe1) + loss ----------------
__global__ void k_sent(const float* __restrict__ x, float* out) {
    int i = blockIdx.x * blockDim.x + threadIdx.x;
    if (i == 0) out[0] = 0.f;
    if (i >= Bb * Dn) return;
    int b = i >> 10, d = i & 1023;
    size_t base = (size_t)(b * Sn) * Dn + d;
    const float* px = x + base;
    const float* m0 = g_moe + base;
    const float* m1 = g_moe + (size_t)Tn * Dn + base;
    float s = 0.f;
    for (int si = 0; si < Sn; si++)
        s += px[si * Dn] + m0[si * Dn] + m1[si * Dn];
    g_sent[i] = s * (1.f / Sn);
}

__global__ void k_loss(const int* __restrict__ y, float* out) {
    int b = blockIdx.x, tid = threadIdx.x;
    __shared__ float red[256];
    const float* s = &g_sent[b * Dn];
    float m = -1e30f;
    for (int i = tid; i < Dn; i += 256) m = fmaxf(m, s[i]);
    red[tid] = m; __syncthreads();
    for (int o = 128; o; o >>= 1) {
        if (tid < o) red[tid] = fmaxf(red[tid], red[tid + o]);
        __syncthreads();
    }
    float mx = red[0]; __syncthreads();
    float sum = 0.f;
    for (int i = tid; i < Dn; i += 256) sum += expf(s[i] - mx);
    red[tid] = sum; __syncthreads();
    for (int o = 128; o; o >>= 1) {
        if (tid < o) red[tid] += red[tid + o];
        __syncthreads();
    }
    if (tid == 0)
        atomicAdd(out, -(s[y[b]] - (mx + logf(red[0]))) * (1.f / Bb));
}

// ---------------- launch ----------------
extern "C" void kernel_launch(void* const* d_in, const int* in_sizes, int n_in,
                              void* d_out, int out_size) {
    const float* x  = (const float*)d_in[0];
    const int*   y  = (const int*)d_in[1];
    const float* W  = (const float*)d_in[2];
    const float* bb = (const float*)d_in[3];
    const float* Wg = (const float*)d_in[4];
    const float* w1 = (const float*)d_in[5];
    const float* b1 = (const float*)d_in[6];
    const float* w2 = (const float*)d_in[7];
    const float* b2 = (const float*)d_in[8];
    float* out = (float*)d_out;

    constexpr int SMEM_LIN = 4 * 128 * 36 * 4;                    // 73728
    constexpr int SMEM_FFN = (2 * 128 * 36 + 2 * 32 * 136) * 4;   // 71680
    static int done = 0;
    if (!done) {
        cudaFuncSetAttribute((const void*)k_lin,
                             cudaFuncAttributeMaxDynamicSharedMemorySize, SMEM_LIN);
        cudaFuncSetAttribute((const void*)pipe_ffn<Dn, Fn, 1>,
                             cudaFuncAttributeMaxDynamicSharedMemorySize, SMEM_FFN);
        cudaFuncSetAttribute((const void*)pipe_ffn<Fn, Dn, 2>,
                             cudaFuncAttributeMaxDynamicSharedMemorySize, SMEM_FFN);
        done = 1;
    }

    k_wc<<<Dn / 256, 256>>>(W, Wg, bb);
    k_init<<<1, 32>>>();
    k_gate2<<<(Tn * 32) / 256, 256>>>(x);
    k_lin<<<dim3(Tn / 128, Dn / 128), 256, SMEM_LIN>>>(x, W, bb);
    k_off<<<1, 1>>>();
    k_scatter<<<Tn / 256, 256>>>();
    pipe_ffn<Dn, Fn, 1><<<dim3(Tn / 128, Fn / 128, En), 256, SMEM_FFN>>>(w1, b1);
    pipe_ffn<Fn, Dn, 2><<<dim3(Tn / 128, Dn / 128, En), 256, SMEM_FFN>>>(w2, b2);
    k_sent<<<(Bb * Dn + 255) / 256, 256>>>(x, out);
    k_loss<<<Bb, 256>>>(y, out);
}

// round 14
// speedup vs baseline: 1.7683x; 1.7683x over previous
#include <cuda_runtime.h>
#include <cuda_fp16.h>
#include <cstdint>

#define Tn 4096   // B*S tokens
#define Dn 1024
#define En 8
#define Fn 4096
#define Bb 8
#define Sn 512

// ---------------- scratch (device globals; no allocations) ----------------
__device__ __half g_linh[Tn * Dn];                 // fp16 lin (feeds ffn1 A)
__device__ __half g_hh[2 * Tn * Fn];               // fp16 hidden
__device__ __half g_w1h[(size_t)En * Fn * Dn];     // w1 conv+transposed [e][n=F][k=D]
__device__ __half g_w2h[(size_t)En * Dn * Fn];     // w2 conv+transposed [e][n=D][k=F]
__device__ float g_moe[2 * Tn * Dn];               // per-topk-slot outputs
__device__ float g_wc[Dn * En];
__device__ float g_bc[En];
__device__ int   g_tok[2 * Tn];
__device__ int   g_tk[2 * Tn];
__device__ float g_tw[2 * Tn];
__device__ int   g_cnt[En], g_off[En], g_fill[En];
__device__ int   g_gi[Tn * 2];
__device__ float g_gw[Tn * 2];
__device__ float g_sent[Bb * Dn];

// ---------------- helpers ----------------
__device__ __forceinline__ uint32_t s2u(const void* p) {
    uint32_t a;
    asm("{ .reg .u64 t; cvta.to.shared.u64 t, %1; cvt.u32.u64 %0, t; }" : "=r"(a) : "l"(p));
    return a;
}
__device__ __forceinline__ void mma8(float* c, const uint32_t* a,
                                     uint32_t b0, uint32_t b1) {
    asm volatile(
        "mma.sync.aligned.m16n8k8.row.col.f32.tf32.tf32.f32 "
        "{%0,%1,%2,%3},{%4,%5,%6,%7},{%8,%9},{%0,%1,%2,%3};"
        : "+f"(c[0]), "+f"(c[1]), "+f"(c[2]), "+f"(c[3])
        : "r"(a[0]), "r"(a[1]), "r"(a[2]), "r"(a[3]), "r"(b0), "r"(b1));
}
__device__ __forceinline__ void mma16h(float* c, const uint32_t* a,
                                       uint32_t b0, uint32_t b1) {
    asm volatile(
        "mma.sync.aligned.m16n8k16.row.col.f32.f16.f16.f32 "
        "{%0,%1,%2,%3},{%4,%5,%6,%7},{%8,%9},{%0,%1,%2,%3};"
        : "+f"(c[0]), "+f"(c[1]), "+f"(c[2]), "+f"(c[3])
        : "r"(a[0]), "r"(a[1]), "r"(a[2]), "r"(a[3]), "r"(b0), "r"(b1));
}
__device__ __forceinline__ void ldmx4(uint32_t* r, uint32_t a) {
    asm volatile("ldmatrix.sync.aligned.m8n8.x4.shared.b16 {%0,%1,%2,%3},[%4];"
                 : "=r"(r[0]), "=r"(r[1]), "=r"(r[2]), "=r"(r[3]) : "r"(a));
}
#define CPA(dst, src) \
    asm volatile("cp.async.cg.shared.global [%0], [%1], 16;" :: "r"(dst), "l"(src) : "memory")
#define CPCOMMIT() asm volatile("cp.async.commit_group;" ::: "memory")
#define CPWAIT0()  asm volatile("cp.async.wait_group 0;" ::: "memory")
#define CPWAIT1()  asm volatile("cp.async.wait_group 1;" ::: "memory")

// ---------------- convert + transpose: [e][R][C] fp32 -> [e][C][R] fp16 ----
__global__ void __launch_bounds__(256) k_ct(const float* __restrict__ src,
                                            __half* __restrict__ dst, int R, int C) {
    __shared__ float t[32][33];
    int e = blockIdx.z;
    const float* s = src + (size_t)e * R * C;
    __half* d = dst + (size_t)e * R * C;
    int c0 = blockIdx.x * 32, r0 = blockIdx.y * 32;
    int tx = threadIdx.x & 31, ty = threadIdx.x >> 5;
#pragma unroll
    for (int i = 0; i < 4; i++)
        t[ty + 8 * i][tx] = s[(size_t)(r0 + ty + 8 * i) * C + c0 + tx];
    __syncthreads();
#pragma unroll
    for (int i = 0; i < 4; i++)
        d[(size_t)(c0 + ty + 8 * i) * R + r0 + tx] = __float2half(t[tx][ty + 8 * i]);
}

// ---------------- Wc = W^T @ Wg (exact fp32), bc = b @ Wg ----------------
__global__ void __launch_bounds__(256) k_wc(const float* __restrict__ W,
                                            const float* __restrict__ Wg,
                                            const float* __restrict__ b) {
    __shared__ float swg[Dn * En];
    for (int i = threadIdx.x; i < Dn * En; i += 256) swg[i] = Wg[i];
    __syncthreads();
    int d = blockIdx.x * 256 + threadIdx.x;
    float acc[En] = {};
    for (int ep = 0; ep < Dn; ep++) {
        float wv = W[(size_t)ep * Dn + d];
        const float* wg = &swg[ep * En];
#pragma unroll
        for (int e = 0; e < En; e++) acc[e] += wv * wg[e];
    }
#pragma unroll
    for (int e = 0; e < En; e++) g_wc[d * En + e] = acc[e];
    if (blockIdx.x == 0 && threadIdx.x < En) {
        float s = 0.f;
        for (int ep = 0; ep < Dn; ep++) s += b[ep] * swg[ep * En + threadIdx.x];
        g_bc[threadIdx.x] = s;
    }
}

__global__ void k_init() {
    if (threadIdx.x < En) g_cnt[threadIdx.x] = 0;
}

// ---------------- gate from x via folded Wc (exact fp32 top-2) -------------
__global__ void k_gate2(const float* __restrict__ x) {
    int warp = (blockIdx.x * blockDim.x + threadIdx.x) >> 5;
    int lane = threadIdx.x & 31;
    if (warp >= Tn) return;
    const float* xr = &x[(size_t)warp * Dn];
    float p[En] = {};
    for (int i = lane; i < Dn; i += 32) {
        float v = xr[i];
        const float* w = &g_wc[i * En];
#pragma unroll
        for (int e = 0; e < En; e++) p[e] += v * w[e];
    }
#pragma unroll
    for (int o = 16; o; o >>= 1)
#pragma unroll
        for (int e = 0; e < En; e++) p[e] += __shfl_xor_sync(0xffffffffu, p[e], o);
    if (lane == 0) {
#pragma unroll
        for (int e = 0; e < En; e++) p[e] += g_bc[e];
        int i1 = 0;
        for (int e = 1; e < En; e++) if (p[e] > p[i1]) i1 = e;
        int i2 = -1;
        for (int e = 0; e < En; e++)
            if (e != i1 && (i2 < 0 || p[e] > p[i2])) i2 = e;
        float w1 = 1.f / (1.f + expf(p[i2] - p[i1]));
        g_gi[warp * 2] = i1; g_gi[warp * 2 + 1] = i2;
        g_gw[warp * 2] = w1; g_gw[warp * 2 + 1] = 1.f - w1;
        atomicAdd(&g_cnt[i1], 1);
        atomicAdd(&g_cnt[i2], 1);
    }
}

__global__ void k_off() {
    int a = 0;
    for (int e = 0; e < En; e++) { g_off[e] = a; a += g_cnt[e]; g_fill[e] = 0; }
}

__global__ void k_scatter() {
    int t = blockIdx.x * blockDim.x + threadIdx.x;
    if (t >= Tn) return;
#pragma unroll
    for (int k = 0; k < 2; k++) {
        int e = g_gi[t * 2 + k];
        int slot = g_off[e] + atomicAdd(&g_fill[e], 1);
        g_tok[slot] = t;
        g_tk[slot]  = k;
        g_tw[slot]  = g_gw[t * 2 + k];
    }
}

// ==== lin = x @ W^T + b : proven tf32 pipelined ldmatrix GEMM -> fp16 out ===
__global__ void __launch_bounds__(256) k_lin(const float* __restrict__ x,
                                             const float* __restrict__ W,
                                             const float* __restrict__ bias)
{
    extern __shared__ float sm[];
    constexpr int STR = 36;
    constexpr uint32_t ASTG = 128 * STR * 4, BSTG = 128 * STR * 4;
    float* Asm = sm;
    float* Bsm = sm + 2 * 128 * STR;
    int row0 = blockIdx.x * 128, col0 = blockIdx.y * 128;
    int tid = threadIdx.x, warp = tid >> 5, lane = tid & 31;
    int warpM = warp >> 1, warpN = warp & 1;
    int grp = lane >> 2, tig = lane & 3;
    int mBase = warpM * 32, nBase = warpN * 64;
    uint32_t Au = s2u(Asm), Bu = s2u(Bsm);

    int ar = tid >> 1, ac = (tid & 1) * 16;
    const float* asrc = x + (size_t)(row0 + ar) * Dn + ac;
    const float* bsrc = W + (size_t)(col0 + ar) * Dn + ac;
    uint32_t aDst0 = Au + ((uint32_t)ar * STR + ac) * 4;
    uint32_t bDst0 = Bu + ((uint32_t)ar * STR + ac) * 4;

    auto stage = [&](int it) {
        int buf = it & 1;
        const float* as = asrc + it * 32;
        const float* bs = bsrc + it * 32;
        uint32_t ad = aDst0 + buf * ASTG, bd = bDst0 + buf * BSTG;
#pragma unroll
        for (int j = 0; j < 4; j++) CPA(ad + j * 16, as + j * 4);
#pragma unroll
        for (int j = 0; j < 4; j++) CPA(bd + j * 16, bs + j * 4);
        CPCOMMIT();
    };
    stage(0);
    stage(1);

    uint32_t aB0 = Au + (uint32_t)((mBase + (lane & 7) + 8 * ((lane >> 3) & 1)) * STR
                                   + 4 * (lane >> 4)) * 4;
    uint32_t aB1 = aB0 + 16 * STR * 4;
    uint32_t bB[4];
#pragma unroll
    for (int p = 0; p < 4; p++)
        bB[p] = Bu + (uint32_t)((nBase + p * 16 + (lane & 7) + 8 * (lane >> 4)) * STR
                                + 4 * ((lane >> 3) & 1)) * 4;

    float cc[2][8][4] = {};
    constexpr int NK = Dn / 32;
    for (int it = 0; it < NK; ++it) {
        if (it < NK - 1) { CPWAIT1(); } else { CPWAIT0(); }
        __syncthreads();
        uint32_t so = (uint32_t)(it & 1) * ASTG;
#pragma unroll
        for (int ks = 0; ks < 32; ks += 8) {
            uint32_t af0[4], af1[4], bf[4][4];
            ldmx4(af0, aB0 + so + ks * 4);
            ldmx4(af1, aB1 + so + ks * 4);
#pragma unroll
            for (int p = 0; p < 4; p++) ldmx4(bf[p], bB[p] + so + ks * 4);
#pragma unroll
            for (int p = 0; p < 4; p++) {
                mma8(cc[0][2 * p],     af0, bf[p][0], bf[p][1]);
                mma8(cc[0][2 * p + 1], af0, bf[p][2], bf[p][3]);
                mma8(cc[1][2 * p],     af1, bf[p][0], bf[p][1]);
                mma8(cc[1][2 * p + 1], af1, bf[p][2], bf[p][3]);
            }
        }
        __syncthreads();
        if (it + 2 < NK) stage(it + 2);
    }
#pragma unroll
    for (int mt = 0; mt < 2; mt++)
#pragma unroll
    for (int half = 0; half < 2; half++) {
        int r = row0 + mBase + mt * 16 + grp + half * 8;
        __half* o = g_linh + (size_t)r * Dn + col0;
#pragma unroll
        for (int nt = 0; nt < 8; nt++) {
            int c = nBase + nt * 8 + 2 * tig;
            float vx = cc[mt][nt][half * 2 + 0] + bias[col0 + c];
            float vy = cc[mt][nt][half * 2 + 1] + bias[col0 + c + 1];
            *(__half2*)(o + c) = __floats2half2_rn(vx, vy);
        }
    }
}

// ==== fp16 m16n8k16 grouped GEMM: 128x128 tile, Kc=32, scalar word feeds ====
// B operands pre-transposed [n][k] fp16 -> packed-k half2 words in smem.
// MODE 1: g_hh = relu(linh[g_tok] @ w1h[e] + b1)      (KD=Dn, NT=Fn)
// MODE 2: g_moe[kk][tok] = gw * (g_hh @ w2h[e] + b2)  (KD=Fn, NT=Dn)
template<int KD, int NT, int MODE>
__global__ void __launch_bounds__(256) ffn_h(const __half* __restrict__ Bw,
                                             const float* __restrict__ bias)
{
    extern __shared__ __half smh[];
    constexpr int STRH = 40;                    // halfs/row (32 data + 8 pad) = 20 words
    constexpr uint32_t STG = 128 * STRH * 2;    // 10240 B per operand per stage
    __half* Ash = smh;                          // [2][128][40]
    __half* Bsh = smh + 2 * 128 * STRH;         // [2][128][40]

    int e = blockIdx.z, cnt = g_cnt[e], row0 = blockIdx.x * 128;
    if (row0 >= cnt) return;
    int off = g_off[e], col0 = blockIdx.y * 128;
    int tid = threadIdx.x, warp = tid >> 5, lane = tid & 31;
    int warpM = warp >> 1, warpN = warp & 1;
    int grp = lane >> 2, tig = lane & 3;
    int mBase = warpM * 32, nBase = warpN * 64;

    uint32_t Au = s2u(Ash), Bu = s2u(Bsh);

    // staging: row ar (2 threads/row, 16 halfs = 32B each)
    int ar = tid >> 1, ach = (tid & 1) * 16;
    const __half* asrc;
    if (MODE == 1) {
        int r = row0 + ar;
        int tok = (r < cnt) ? g_tok[off + r] : g_tok[off];
        asrc = g_linh + (size_t)tok * KD;
    } else {
        int s = off + row0 + ar; if (s >= 2 * Tn) s = 0;
        asrc = g_hh + (size_t)s * KD;
    }
    const __half* bsrc = Bw + (size_t)e * KD * NT + (size_t)(col0 + ar) * KD;
    asrc += ach; bsrc += ach;
    uint32_t aDst0 = Au + ((uint32_t)ar * STRH + ach) * 2;
    uint32_t bDst0 = Bu + ((uint32_t)ar * STRH + ach) * 2;

    auto stage = [&](int it) {
        int buf = it & 1;
        const __half* as = asrc + it * 32;
        const __half* bs = bsrc + it * 32;
        uint32_t ad = aDst0 + buf * STG, bd = bDst0 + buf * STG;
#pragma unroll
        for (int j = 0; j < 2; j++) CPA(ad + j * 16, as + j * 8);
#pragma unroll
        for (int j = 0; j < 2; j++) CPA(bd + j * 16, bs + j * 8);
        CPCOMMIT();
    };
    stage(0);
    stage(1);

    float cc[2][8][4] = {};
    constexpr int NK = KD / 32;
    for (int it = 0; it < NK; ++it) {
        if (it == NK - 1) { CPWAIT0(); } else { CPWAIT1(); }
        __syncthreads();
        int buf = it & 1;
        const uint32_t* Af = (const uint32_t*)(Ash + buf * 128 * STRH);
        const uint32_t* Bf = (const uint32_t*)(Bsh + buf * 128 * STRH);
#pragma unroll
        for (int kw = 0; kw < 16; kw += 8) {    // two k16 steps (word offsets 0, 8)
            uint32_t af[2][4];
#pragma unroll
            for (int mt = 0; mt < 2; mt++) {
                int m = mBase + mt * 16 + grp;
                af[mt][0] = Af[m * 20 + kw + tig];
                af[mt][1] = Af[(m + 8) * 20 + kw + tig];
                af[mt][2] = Af[m * 20 + kw + tig + 4];
                af[mt][3] = Af[(m + 8) * 20 + kw + tig + 4];
            }
#pragma unroll
            for (int nt = 0; nt < 8; nt++) {
                int n = nBase + nt * 8 + grp;
                uint32_t b0 = Bf[n * 20 + kw + tig];
                uint32_t b1 = Bf[n * 20 + kw + tig + 4];
                mma16h(cc[0][nt], af[0], b0, b1);
                mma16h(cc[1][nt], af[1], b0, b1);
            }
        }
        __syncthreads();
        if (it + 2 < NK) stage(it + 2);
    }

#pragma unroll
    for (int mt = 0; mt < 2; mt++)
#pragma unroll
    for (int half = 0; half < 2; half++) {
        int r = row0 + mBase + mt * 16 + grp + half * 8;
        if (r >= cnt) continue;
        int slot = off + r;
        if (MODE == 1) {
            __half* o = g_hh + (size_t)slot * Fn + col0;
#pragma unroll
            for (int nt = 0; nt < 8; nt++) {
                int c = nBase + nt * 8 + 2 * tig;
                float vx = fmaxf(cc[mt][nt][half * 2 + 0] + bias[e * Fn + col0 + c], 0.f);
                float vy = fmaxf(cc[mt][nt][half * 2 + 1] + bias[e * Fn + col0 + c + 1], 0.f);
                *(__half2*)(o + c) = __floats2half2_rn(vx, vy);
            }
        } else {
            int tok = g_tok[slot];
            int kk  = g_tk[slot];
            float gw = g_tw[slot];
            float* o = g_moe + ((size_t)kk * Tn + tok) * Dn + col0;
#pragma unroll
            for (int nt = 0; nt < 8; nt++) {
                int c = nBase + nt * 8 + 2 * tig;
                float2 v;
                v.x = gw * (cc[mt][nt][half * 2 + 0] + bias[e * Dn + col0 + c]);
                v.y = gw * (cc[mt][nt][half * 2 + 1] + bias[e * Dn + col0 + c + 1]);
                *(float2*)(o + c) = v;
            }
        }
    }
}

// ---------------- mean pool (x + moe0 + moe1) + loss ----------------
__global__ void k_sent(const float* __restrict__ x, float* out) {
    int i = blockIdx.x * blockDim.x + threadIdx.x;
    if (i == 0) out[0] = 0.f;
    if (i >= Bb * Dn) return;
    int b = i >> 10, d = i & 1023;
    size_t base = (size_t)(b * Sn) * Dn + d;
    const float* px = x + base;
    const float* m0 = g_moe + base;
    const float* m1 = g_moe + (size_t)Tn * Dn + base;
    float s = 0.f;
    for (int si = 0; si < Sn; si++)
        s += px[si * Dn] + m0[si * Dn] + m1[si * Dn];
    g_sent[i] = s * (1.f / Sn);
}

__global__ void k_loss(const int* __restrict__ y, float* out) {
    int b = blockIdx.x, tid = threadIdx.x;
    __shared__ float red[256];
    const float* s = &g_sent[b * Dn];
    float m = -1e30f;
    for (int i = tid; i < Dn; i += 256) m = fmaxf(m, s[i]);
    red[tid] = m; __syncthreads();
    for (int o = 128; o; o >>= 1) {
        if (tid < o) red[tid] = fmaxf(red[tid], red[tid + o]);
        __syncthreads();
    }
    float mx = red[0]; __syncthreads();
    float sum = 0.f;
    for (int i = tid; i < Dn; i += 256) sum += expf(s[i] - mx);
    red[tid] = sum; __syncthreads();
    for (int o = 128; o; o >>= 1) {
        if (tid < o) red[tid] += red[tid + o];
        __syncthreads();
    }
    if (tid == 0)
        atomicAdd(out, -(s[y[b]] - (mx + logf(red[0]))) * (1.f / Bb));
}

// ---------------- launch ----------------
extern "C" void kernel_launch(void* const* d_in, const int* in_sizes, int n_in,
                              void* d_out, int out_size) {
    const float* x  = (const float*)d_in[0];
    const int*   y  = (const int*)d_in[1];
    const float* W  = (const float*)d_in[2];
    const float* bb = (const float*)d_in[3];
    const float* Wg = (const float*)d_in[4];
    const float* w1 = (const float*)d_in[5];
    const float* b1 = (const float*)d_in[6];
    const float* w2 = (const float*)d_in[7];
    const float* b2 = (const float*)d_in[8];
    float* out = (float*)d_out;

    constexpr int SMEM_LIN = 4 * 128 * 36 * 4;   // 73728 B
    constexpr int SMEM_FFN = 4 * 128 * 40 * 2;   // 40960 B
    static int done = 0;
    if (!done) {
        cudaFuncSetAttribute((const void*)k_lin,
                             cudaFuncAttributeMaxDynamicSharedMemorySize, SMEM_LIN);
        done = 1;
    }

    __half* w1h; cudaGetSymbolAddress((void**)&w1h, g_w1h);
    __half* w2h; cudaGetSymbolAddress((void**)&w2h, g_w2h);
    k_ct<<<dim3(Fn / 32, Dn / 32, En), 256>>>(w1, w1h, Dn, Fn);  // [D][F]->[F][D]
    k_ct<<<dim3(Dn / 32, Fn / 32, En), 256>>>(w2, w2h, Fn, Dn);  // [F][D]->[D][F]

    k_wc<<<Dn / 256, 256>>>(W, Wg, bb);
    k_init<<<1, 32>>>();
    k_gate2<<<(Tn * 32) / 256, 256>>>(x);
    k_lin<<<dim3(Tn / 128, Dn / 128), 256, SMEM_LIN>>>(x, W, bb);
    k_off<<<1, 1>>>();
    k_scatter<<<Tn / 256, 256>>>();
    ffn_h<Dn, Fn, 1><<<dim3(Tn / 128, Fn / 128, En), 256, SMEM_FFN>>>(w1h, b1);
    ffn_h<Fn, Dn, 2><<<dim3(Tn / 128, Dn / 128, En), 256, SMEM_FFN>>>(w2h, b2);
    k_sent<<<(Bb * Dn + 255) / 256, 256>>>(x, out);
    k_loss<<<Bb, 256>>>(y, out);
}

// round 15
// speedup vs baseline: 1.9172x; 1.0842x over previous
#include <cuda_runtime.h>
#include <cuda_fp16.h>
#include <cstdint>

#define Tn 4096   // B*S tokens
#define Dn 1024
#define En 8
#define Fn 4096
#define Bb 8
#define Sn 512

// ---------------- scratch (device globals; no allocations) ----------------
__device__ __half g_xh[Tn * Dn];                   // fp16 x (lin A operand)
__device__ __half g_Wh[Dn * Dn];                   // fp16 W [n][k] (lin B operand)
__device__ __half g_linh[Tn * Dn];                 // fp16 lin
__device__ __half g_hh[2 * Tn * Fn];               // fp16 hidden
__device__ __half g_w1h[(size_t)En * Fn * Dn];     // w1 conv+transposed [e][n=F][k=D]
__device__ __half g_w2h[(size_t)En * Dn * Fn];     // w2 conv+transposed [e][n=D][k=F]
__device__ float g_moe[2 * Tn * Dn];               // per-topk-slot outputs
__device__ float g_wc[Dn * En];
__device__ float g_bc[En];
__device__ int   g_tok[2 * Tn];
__device__ int   g_tk[2 * Tn];
__device__ float g_tw[2 * Tn];
__device__ int   g_cnt[En], g_off[En], g_fill[En];
__device__ int   g_gi[Tn * 2];
__device__ float g_gw[Tn * 2];
__device__ float g_sent[Bb * Dn];

// ---------------- helpers ----------------
__device__ __forceinline__ uint32_t s2u(const void* p) {
    uint32_t a;
    asm("{ .reg .u64 t; cvta.to.shared.u64 t, %1; cvt.u32.u64 %0, t; }" : "=r"(a) : "l"(p));
    return a;
}
__device__ __forceinline__ void mma16h(float* c, const uint32_t* a,
                                       uint32_t b0, uint32_t b1) {
    asm volatile(
        "mma.sync.aligned.m16n8k16.row.col.f32.f16.f16.f32 "
        "{%0,%1,%2,%3},{%4,%5,%6,%7},{%8,%9},{%0,%1,%2,%3};"
        : "+f"(c[0]), "+f"(c[1]), "+f"(c[2]), "+f"(c[3])
        : "r"(a[0]), "r"(a[1]), "r"(a[2]), "r"(a[3]), "r"(b0), "r"(b1));
}
__device__ __forceinline__ void ldmx4(uint32_t* r, uint32_t a) {
    asm volatile("ldmatrix.sync.aligned.m8n8.x4.shared.b16 {%0,%1,%2,%3},[%4];"
                 : "=r"(r[0]), "=r"(r[1]), "=r"(r[2]), "=r"(r[3]) : "r"(a));
}
#define CPA(dst, src) \
    asm volatile("cp.async.cg.shared.global [%0], [%1], 16;" :: "r"(dst), "l"(src) : "memory")
#define CPCOMMIT() asm volatile("cp.async.commit_group;" ::: "memory")
#define CPWAIT0()  asm volatile("cp.async.wait_group 0;" ::: "memory")
#define CPWAIT1()  asm volatile("cp.async.wait_group 1;" ::: "memory")

// ---------------- elementwise fp32 -> fp16 ----------------
__global__ void __launch_bounds__(256) k_cvt(const float* __restrict__ s,
                                             __half* __restrict__ d, int n) {
    int i = (blockIdx.x * blockDim.x + threadIdx.x) * 4;
    int st = gridDim.x * blockDim.x * 4;
    for (; i < n; i += st) {
        float4 v = *(const float4*)(s + i);
        *(__half2*)(d + i)     = __floats2half2_rn(v.x, v.y);
        *(__half2*)(d + i + 2) = __floats2half2_rn(v.z, v.w);
    }
}

// ---------------- convert + transpose: [e][R][C] fp32 -> [e][C][R] fp16 ----
__global__ void __launch_bounds__(256) k_ct(const float* __restrict__ src,
                                            __half* __restrict__ dst, int R, int C) {
    __shared__ float t[32][33];
    int e = blockIdx.z;
    const float* s = src + (size_t)e * R * C;
    __half* d = dst + (size_t)e * R * C;
    int c0 = blockIdx.x * 32, r0 = blockIdx.y * 32;
    int tx = threadIdx.x & 31, ty = threadIdx.x >> 5;
#pragma unroll
    for (int i = 0; i < 4; i++)
        t[ty + 8 * i][tx] = s[(size_t)(r0 + ty + 8 * i) * C + c0 + tx];
    __syncthreads();
#pragma unroll
    for (int i = 0; i < 4; i++)
        d[(size_t)(c0 + ty + 8 * i) * R + r0 + tx] = __float2half(t[tx][ty + 8 * i]);
}

// ---------------- Wc = W^T @ Wg (exact fp32), bc = b @ Wg ----------------
__global__ void __launch_bounds__(256) k_wc(const float* __restrict__ W,
                                            const float* __restrict__ Wg,
                                            const float* __restrict__ b) {
    __shared__ float swg[Dn * En];
    for (int i = threadIdx.x; i < Dn * En; i += 256) swg[i] = Wg[i];
    __syncthreads();
    int d = blockIdx.x * 256 + threadIdx.x;
    float acc[En] = {};
    for (int ep = 0; ep < Dn; ep++) {
        float wv = W[(size_t)ep * Dn + d];
        const float* wg = &swg[ep * En];
#pragma unroll
        for (int e = 0; e < En; e++) acc[e] += wv * wg[e];
    }
#pragma unroll
    for (int e = 0; e < En; e++) g_wc[d * En + e] = acc[e];
    if (blockIdx.x == 0 && threadIdx.x < En) {
        float s = 0.f;
        for (int ep = 0; ep < Dn; ep++) s += b[ep] * swg[ep * En + threadIdx.x];
        g_bc[threadIdx.x] = s;
    }
}

__global__ void k_init() {
    if (threadIdx.x < En) g_cnt[threadIdx.x] = 0;
}

// ---------------- gate from x via folded Wc (exact fp32 top-2) -------------
__global__ void k_gate2(const float* __restrict__ x) {
    int warp = (blockIdx.x * blockDim.x + threadIdx.x) >> 5;
    int lane = threadIdx.x & 31;
    if (warp >= Tn) return;
    const float* xr = &x[(size_t)warp * Dn];
    float p[En] = {};
    for (int i = lane; i < Dn; i += 32) {
        float v = xr[i];
        const float* w = &g_wc[i * En];
#pragma unroll
        for (int e = 0; e < En; e++) p[e] += v * w[e];
    }
#pragma unroll
    for (int o = 16; o; o >>= 1)
#pragma unroll
        for (int e = 0; e < En; e++) p[e] += __shfl_xor_sync(0xffffffffu, p[e], o);
    if (lane == 0) {
#pragma unroll
        for (int e = 0; e < En; e++) p[e] += g_bc[e];
        int i1 = 0;
        for (int e = 1; e < En; e++) if (p[e] > p[i1]) i1 = e;
        int i2 = -1;
        for (int e = 0; e < En; e++)
            if (e != i1 && (i2 < 0 || p[e] > p[i2])) i2 = e;
        float w1 = 1.f / (1.f + expf(p[i2] - p[i1]));
        g_gi[warp * 2] = i1; g_gi[warp * 2 + 1] = i2;
        g_gw[warp * 2] = w1; g_gw[warp * 2 + 1] = 1.f - w1;
        atomicAdd(&g_cnt[i1], 1);
        atomicAdd(&g_cnt[i2], 1);
    }
}

__global__ void k_off() {
    int a = 0;
    for (int e = 0; e < En; e++) { g_off[e] = a; a += g_cnt[e]; g_fill[e] = 0; }
}

__global__ void k_scatter() {
    int t = blockIdx.x * blockDim.x + threadIdx.x;
    if (t >= Tn) return;
#pragma unroll
    for (int k = 0; k < 2; k++) {
        int e = g_gi[t * 2 + k];
        int slot = g_off[e] + atomicAdd(&g_fill[e], 1);
        g_tok[slot] = t;
        g_tk[slot]  = k;
        g_tw[slot]  = g_gw[t * 2 + k];
    }
}

// ==== fp16 m16n8k16 GEMM, ldmatrix feeds: 128x128 tile, Kc=32 ==============
// B operands [n][k] fp16 (k-contiguous).
// MODE 0: g_linh = xh @ Wh^T + b                      (KD=Dn, NT=Dn)
// MODE 1: g_hh = relu(linh[g_tok] @ w1h[e] + b1)      (KD=Dn, NT=Fn)
// MODE 2: g_moe[kk][tok] = gw * (g_hh @ w2h[e] + b2)  (KD=Fn, NT=Dn)
template<int KD, int NT, int MODE>
__global__ void __launch_bounds__(256) ffn_h(const __half* __restrict__ Bw,
                                             const float* __restrict__ bias)
{
    extern __shared__ __half smh[];
    constexpr int STRH = 40;                    // halfs/row: 80B rows, ldmatrix conflict-free
    constexpr uint32_t STG = 128 * STRH * 2;    // 10240 B per operand per stage
    __half* Ash = smh;                          // [2][128][40]
    __half* Bsh = smh + 2 * 128 * STRH;         // [2][128][40]

    int e = (MODE == 0) ? 0 : blockIdx.z;
    int cnt = (MODE == 0) ? Tn : g_cnt[e];
    int row0 = blockIdx.x * 128;
    if (MODE != 0 && row0 >= cnt) return;
    int off = (MODE == 0) ? 0 : g_off[e];
    int col0 = blockIdx.y * 128;
    int tid = threadIdx.x, warp = tid >> 5, lane = tid & 31;
    int warpM = warp >> 1, warpN = warp & 1;
    int grp = lane >> 2, tig = lane & 3;
    int mBase = warpM * 32, nBase = warpN * 64;

    uint32_t Au = s2u(Ash), Bu = s2u(Bsh);

    // staging: row ar (2 threads/row, 16 halfs = 32B each)
    int ar = tid >> 1, ach = (tid & 1) * 16;
    const __half* asrc;
    if (MODE == 0) {
        asrc = g_xh + (size_t)(row0 + ar) * KD;
    } else if (MODE == 1) {
        int r = row0 + ar;
        int tok = (r < cnt) ? g_tok[off + r] : g_tok[off];
        asrc = g_linh + (size_t)tok * KD;
    } else {
        int s = off + row0 + ar; if (s >= 2 * Tn) s = 0;
        asrc = g_hh + (size_t)s * KD;
    }
    const __half* bsrc = Bw + (MODE != 0 ? (size_t)e * Dn * Fn : 0)
                            + (size_t)(col0 + ar) * KD;
    asrc += ach; bsrc += ach;
    uint32_t aDst0 = Au + ((uint32_t)ar * STRH + ach) * 2;
    uint32_t bDst0 = Bu + ((uint32_t)ar * STRH + ach) * 2;

    auto stage = [&](int it) {
        int buf = it & 1;
        const __half* as = asrc + it * 32;
        const __half* bs = bsrc + it * 32;
        uint32_t ad = aDst0 + buf * STG, bd = bDst0 + buf * STG;
#pragma unroll
        for (int j = 0; j < 2; j++) CPA(ad + j * 16, as + j * 8);
#pragma unroll
        for (int j = 0; j < 2; j++) CPA(bd + j * 16, bs + j * 8);
        CPCOMMIT();
    };
    stage(0);
    stage(1);

    // ldmatrix lane bases: rows at 80B stride, k-half select via lane>>4 (+16B)
    uint32_t aB0 = Au + (uint32_t)(mBase + (lane & 7) + 8 * ((lane >> 3) & 1)) * (STRH * 2)
                      + (lane >> 4) * 16;
    uint32_t aB1 = aB0 + 16 * STRH * 2;
    uint32_t bB[4];
#pragma unroll
    for (int p = 0; p < 4; p++)
        bB[p] = Bu + (uint32_t)(nBase + p * 16 + (lane & 7) + 8 * ((lane >> 3) & 1)) * (STRH * 2)
                   + (lane >> 4) * 16;

    float cc[2][8][4] = {};
    constexpr int NK = KD / 32;
    for (int it = 0; it < NK; ++it) {
        if (it == NK - 1) { CPWAIT0(); } else { CPWAIT1(); }
        __syncthreads();
        uint32_t so = (uint32_t)(it & 1) * STG;
#pragma unroll
        for (int ks = 0; ks < 2; ks++) {        // two k16 steps per 32-k chunk
            uint32_t kb = ks * 32;              // 16 halfs = 32 bytes
            uint32_t af0[4], af1[4], bf[4][4];
            ldmx4(af0, aB0 + so + kb);
            ldmx4(af1, aB1 + so + kb);
#pragma unroll
            for (int p = 0; p < 4; p++) ldmx4(bf[p], bB[p] + so + kb);
            // bf[p]: reg0 = b0 of nt=2p, reg1 = b0 of nt=2p+1, reg2/3 = b1's
#pragma unroll
            for (int p = 0; p < 4; p++) {
                mma16h(cc[0][2 * p],     af0, bf[p][0], bf[p][2]);
                mma16h(cc[0][2 * p + 1], af0, bf[p][1], bf[p][3]);
                mma16h(cc[1][2 * p],     af1, bf[p][0], bf[p][2]);
                mma16h(cc[1][2 * p + 1], af1, bf[p][1], bf[p][3]);
            }
        }
        __syncthreads();
        if (it + 2 < NK) stage(it + 2);
    }

#pragma unroll
    for (int mt = 0; mt < 2; mt++)
#pragma unroll
    for (int half = 0; half < 2; half++) {
        int r = row0 + mBase + mt * 16 + grp + half * 8;
        if (MODE != 0 && r >= cnt) continue;
        int slot = off + r;
        if (MODE == 0) {
            __half* o = g_linh + (size_t)r * Dn + col0;
#pragma unroll
            for (int nt = 0; nt < 8; nt++) {
                int c = nBase + nt * 8 + 2 * tig;
                float vx = cc[mt][nt][half * 2 + 0] + bias[col0 + c];
                float vy = cc[mt][nt][half * 2 + 1] + bias[col0 + c + 1];
                *(__half2*)(o + c) = __floats2half2_rn(vx, vy);
            }
        } else if (MODE == 1) {
            __half* o = g_hh + (size_t)slot * Fn + col0;
#pragma unroll
            for (int nt = 0; nt < 8; nt++) {
                int c = nBase + nt * 8 + 2 * tig;
                float vx = fmaxf(cc[mt][nt][half * 2 + 0] + bias[e * Fn + col0 + c], 0.f);
                float vy = fmaxf(cc[mt][nt][half * 2 + 1] + bias[e * Fn + col0 + c + 1], 0.f);
                *(__half2*)(o + c) = __floats2half2_rn(vx, vy);
            }
        } else {
            int tok = g_tok[slot];
            int kk  = g_tk[slot];
            float gw = g_tw[slot];
            float* o = g_moe + ((size_t)kk * Tn + tok) * Dn + col0;
#pragma unroll
            for (int nt = 0; nt < 8; nt++) {
                int c = nBase + nt * 8 + 2 * tig;
                float2 v;
                v.x = gw * (cc[mt][nt][half * 2 + 0] + bias[e * Dn + col0 + c]);
                v.y = gw * (cc[mt][nt][half * 2 + 1] + bias[e * Dn + col0 + c + 1]);
                *(float2*)(o + c) = v;
            }
        }
    }
}

// ---------------- mean pool (x + moe0 + moe1) + loss ----------------
__global__ void k_sent(const float* __restrict__ x, float* out) {
    int i = blockIdx.x * blockDim.x + threadIdx.x;
    if (i == 0) out[0] = 0.f;
    if (i >= Bb * Dn) return;
    int b = i >> 10, d = i & 1023;
    size_t base = (size_t)(b * Sn) * Dn + d;
    const float* px = x + base;
    const float* m0 = g_moe + base;
    const float* m1 = g_moe + (size_t)Tn * Dn + base;
    float s = 0.f;
    for (int si = 0; si < Sn; si++)
        s += px[si * Dn] + m0[si * Dn] + m1[si * Dn];
    g_sent[i] = s * (1.f / Sn);
}

__global__ void k_loss(const int* __restrict__ y, float* out) {
    int b = blockIdx.x, tid = threadIdx.x;
    __shared__ float red[256];
    const float* s = &g_sent[b * Dn];
    float m = -1e30f;
    for (int i = tid; i < Dn; i += 256) m = fmaxf(m, s[i]);
    red[tid] = m; __syncthreads();
    for (int o = 128; o; o >>= 1) {
        if (tid < o) red[tid] = fmaxf(red[tid], red[tid + o]);
        __syncthreads();
    }
    float mx = red[0]; __syncthreads();
    float sum = 0.f;
    for (int i = tid; i < Dn; i += 256) sum += expf(s[i] - mx);
    red[tid] = sum; __syncthreads();
    for (int o = 128; o; o >>= 1) {
        if (tid < o) red[tid] += red[tid + o];
        __syncthreads();
    }
    if (tid == 0)
        atomicAdd(out, -(s[y[b]] - (mx + logf(red[0]))) * (1.f / Bb));
}

// ---------------- launch ----------------
extern "C" void kernel_launch(void* const* d_in, const int* in_sizes, int n_in,
                              void* d_out, int out_size) {
    const float* x  = (const float*)d_in[0];
    const int*   y  = (const int*)d_in[1];
    const float* W  = (const float*)d_in[2];
    const float* bb = (const float*)d_in[3];
    const float* Wg = (const float*)d_in[4];
    const float* w1 = (const float*)d_in[5];
    const float* b1 = (const float*)d_in[6];
    const float* w2 = (const float*)d_in[7];
    const float* b2 = (const float*)d_in[8];
    float* out = (float*)d_out;

    constexpr int SMEM_FFN = 4 * 128 * 40 * 2;   // 40960 B

    __half* xh;  cudaGetSymbolAddress((void**)&xh, g_xh);
    __half* Wh;  cudaGetSymbolAddress((void**)&Wh, g_Wh);
    __half* w1h; cudaGetSymbolAddress((void**)&w1h, g_w1h);
    __half* w2h; cudaGetSymbolAddress((void**)&w2h, g_w2h);

    k_cvt<<<1024, 256>>>(x, xh, Tn * Dn);
    k_cvt<<<1024, 256>>>(W, Wh, Dn * Dn);
    k_ct<<<dim3(Fn / 32, Dn / 32, En), 256>>>(w1, w1h, Dn, Fn);  // [D][F]->[F][D]
    k_ct<<<dim3(Dn / 32, Fn / 32, En), 256>>>(w2, w2h, Fn, Dn);  // [F][D]->[D][F]

    k_wc<<<Dn / 256, 256>>>(W, Wg, bb);
    k_init<<<1, 32>>>();
    k_gate2<<<(Tn * 32) / 256, 256>>>(x);
    ffn_h<Dn, Dn, 0><<<dim3(Tn / 128, Dn / 128, 1), 256, SMEM_FFN>>>(Wh, bb);
    k_off<<<1, 1>>>();
    k_scatter<<<Tn / 256, 256>>>();
    ffn_h<Dn, Fn, 1><<<dim3(Tn / 128, Fn / 128, En), 256, SMEM_FFN>>>(w1h, b1);
    ffn_h<Fn, Dn, 2><<<dim3(Tn / 128, Dn / 128, En), 256, SMEM_FFN>>>(w2h, b2);
    k_sent<<<(Bb * Dn + 255) / 256, 256>>>(x, out);
    k_loss<<<Bb, 256>>>(y, out);
}